// round 8
// baseline (speedup 1.0000x reference)
#include <cuda_runtime.h>
#include <cuda_fp16.h>
#include <math.h>
#include <stdint.h>

#define T 2048
#define H 1024
#define F 4096
#define E 8

// ---------------- scratch (static device globals; no allocation) ----------------
__device__ int    g_cnt[E];
__device__ int    g_tok[E][T];
__device__ float  g_wt[E][T];
__device__ __half g_act[(size_t)E * T * F];      // fp16 activation scratch
__device__ __half c_hs[(size_t)T * H];           // fp16 copy of hidden_states

// ================= family-safe PTX helpers =================
__device__ __forceinline__ uint32_t smem_u32(const void* p) {
    uint32_t a;
    asm("{ .reg .u64 t; cvta.to.shared.u64 t, %1; cvt.u32.u64 %0, t; }" : "=r"(a) : "l"(p));
    return a;
}
// d += a * b  (m16n8k16, fp16 inputs, fp32 accum)
__device__ __forceinline__ void mma_f16(float* d, const uint32_t* a, const uint32_t* b) {
    asm volatile(
        "mma.sync.aligned.m16n8k16.row.col.f32.f16.f16.f32 "
        "{%0,%1,%2,%3}, {%4,%5,%6,%7}, {%8,%9}, {%0,%1,%2,%3};"
        : "+f"(d[0]), "+f"(d[1]), "+f"(d[2]), "+f"(d[3])
        : "r"(a[0]), "r"(a[1]), "r"(a[2]), "r"(a[3]), "r"(b[0]), "r"(b[1]));
}
// warp-collective: load 4 8x8 b16 matrices (fragment regs)
__device__ __forceinline__ void ldsm4(uint32_t& r0, uint32_t& r1, uint32_t& r2, uint32_t& r3,
                                      uint32_t addr) {
    asm volatile("ldmatrix.sync.aligned.m8n8.x4.shared.b16 {%0,%1,%2,%3}, [%4];"
                 : "=r"(r0), "=r"(r1), "=r"(r2), "=r"(r3) : "r"(addr));
}
__device__ __forceinline__ void cpa16(uint32_t dst, const void* src, uint32_t sz) {
    asm volatile("cp.async.cg.shared.global [%0], [%1], 16, %2;"
                 :: "r"(dst), "l"(src), "r"(sz) : "memory");
}
#define CPA_COMMIT() asm volatile("cp.async.commit_group;" ::: "memory")
#define CPA_WAIT0()  asm volatile("cp.async.wait_group 0;" ::: "memory")

__device__ __forceinline__ uint32_t h2u(float x, float y) {
    __half2 h = __floats2half2_rn(x, y);
    return *reinterpret_cast<uint32_t*>(&h);
}
__device__ __forceinline__ void sts128(uint32_t addr, uint32_t a, uint32_t b,
                                       uint32_t c, uint32_t d) {
    asm volatile("st.shared.v4.b32 [%0], {%1,%2,%3,%4};"
                 :: "r"(addr), "r"(a), "r"(b), "r"(c), "r"(d) : "memory");
}

// fp16 SMEM tile pitch: 72 halfs (144B). ldmatrix rows hit banks 4r mod 32 -> conflict-free.
#define PH 72
#define BK 64
#define NTHREADS 384   // warps 0-7 compute, 8-11 produce

// ---------------- init + hs convert (merged) ----------------
__global__ void init_cvt_kernel(float* __restrict__ out,
                                const float4* __restrict__ hs, uint2* __restrict__ dhs) {
    int idx = blockIdx.x * blockDim.x + threadIdx.x;
    if (idx < E) g_cnt[idx] = 0;
    int stride = gridDim.x * blockDim.x;
    for (int i = idx; i < T * H; i += stride) out[i] = 0.0f;
    for (int i = idx; i < T * H / 4; i += stride) {
        float4 v = hs[i];
        uint2 o;
        o.x = h2u(v.x, v.y);
        o.y = h2u(v.z, v.w);
        dhs[i] = o;
    }
}

// ---------------- router (exact fp32) ----------------
__global__ void router_kernel(const float* __restrict__ hs, const float* __restrict__ gw) {
    int t = blockIdx.x;
    int tid = threadIdx.x;
    int w = tid >> 5, lane = tid & 31;
    const float* hrow = hs + (size_t)t * H;
    const float* grow = gw + (size_t)w * H;
    float s = 0.0f;
    for (int j = lane; j < H; j += 32) s += hrow[j] * grow[j];
    #pragma unroll
    for (int o = 16; o; o >>= 1) s += __shfl_xor_sync(0xffffffffu, s, o);
    __shared__ float s_logit[E];
    if (lane == 0) s_logit[w] = s;
    __syncthreads();
    if (tid == 0) {
        float l[E], m = -1e30f;
        #pragma unroll
        for (int e = 0; e < E; e++) {
            l[e] = 30.0f * tanhf(s_logit[e] * (1.0f / 30.0f));
            m = fmaxf(m, l[e]);
        }
        float p[E], sum = 0.0f;
        #pragma unroll
        for (int e = 0; e < E; e++) { p[e] = expf(l[e] - m); sum += p[e]; }
        float inv = 1.0f / sum;
        #pragma unroll
        for (int e = 0; e < E; e++) p[e] *= inv;
        int e1 = 0;
        #pragma unroll
        for (int e = 1; e < E; e++) if (p[e] > p[e1]) e1 = e;
        int e2 = (e1 == 0) ? 1 : 0;
        #pragma unroll
        for (int e = 0; e < E; e++) if (e != e1 && p[e] > p[e2]) e2 = e;
        int pos1 = atomicAdd(&g_cnt[e1], 1);
        g_tok[e1][pos1] = t; g_wt[e1][pos1] = p[e1];
        int pos2 = atomicAdd(&g_cnt[e2], 1);
        g_tok[e2][pos2] = t; g_wt[e2][pos2] = p[e2];
    }
}

// ================= gemm1: act = gelu(h@w1^T) * (h@w3^T), warp-specialized =================
// CTA 128m x 64n, BK=64. Warps 0-7 compute (warp 32x32, dual acc), warps 8-11 produce:
//   A from c_hs (fp16 cp.async, 128 rows -> 8 iters of 128 threads),
//   B1/B3 from fp32 w1/w3 (LDG.128 -> cvt -> STS.128, 64 rows -> 4 iters).
// stage: A 128*144 + B1 64*144 + B3 64*144 = 36864B; 2 stages = 73728B.
#define G1_STAGE_B 36864u
#define G1_OFF_B1  18432u
#define G1_OFF_B3  27648u
#define G1_SMEM    (2u * G1_STAGE_B)

__global__ __launch_bounds__(NTHREADS, 1) void gemm1_ws(const float* __restrict__ w1,
                                                        const float* __restrict__ w3) {
    extern __shared__ __half smem[];
    __shared__ int s_tok[128];

    int e = blockIdx.z;
    int cnt = g_cnt[e];
    int i0 = blockIdx.y * 128;
    if (i0 >= cnt) return;
    int n0 = blockIdx.x * 64;
    int tid = threadIdx.x;
    int wid = tid >> 5, lane = tid & 31;
    int g = lane >> 2, t4 = lane & 3;
    int wm = wid & 3, wn = (wid >> 2) & 1;   // compute-warp tile: m 32*wm, n 32*wn

    if (tid < 128) {
        int i = i0 + tid;
        s_tok[tid] = (i < cnt) ? g_tok[e][i] : -1;
    }
    __syncthreads();

    uint32_t sb = smem_u32(smem);
    const float* w1g = w1 + ((size_t)e * F + n0) * H;
    const float* w3g = w3 + ((size_t)e * F + n0) * H;

    // ---- producer: fill stage buf with K-tile kc ----
    int ptid = tid - 256;    // 0..127 for producer warps
    auto produce = [&](int kc, int buf) {
        int k0 = kc * BK;
        uint32_t bb = sb + (uint32_t)buf * G1_STAGE_B;
        // A: 128 rows x 8 chunks of 16B (fp16), gathered. 1024 ids / 128 thr = 8 iters.
        #pragma unroll
        for (int i = 0; i < 8; i++) {
            int id = ptid + i * 128;
            int row = id >> 3, c8 = id & 7;
            int tok = s_tok[row];
            const __half* src = (tok >= 0) ? c_hs + (size_t)tok * H + k0 + c8 * 8 : c_hs;
            cpa16(bb + (uint32_t)(row * 144 + c8 * 16), src, tok >= 0 ? 16u : 0u);
        }
        CPA_COMMIT();
        // B1+B3: 64 rows x 8 fp32-chunks of 32B each (512 ids / 128 thr = 4 iters);
        // batch all LDGs, then cvt+STS
        float4 r[16];
        #pragma unroll
        for (int i = 0; i < 4; i++) {
            int id = ptid + i * 128;
            int row = id >> 3, c8 = id & 7;
            const float* p1 = w1g + (size_t)row * H + k0 + c8 * 8;
            r[2 * i]     = *reinterpret_cast<const float4*>(p1);
            r[2 * i + 1] = *reinterpret_cast<const float4*>(p1 + 4);
            const float* p3 = w3g + (size_t)row * H + k0 + c8 * 8;
            r[8 + 2 * i]     = *reinterpret_cast<const float4*>(p3);
            r[8 + 2 * i + 1] = *reinterpret_cast<const float4*>(p3 + 4);
        }
        #pragma unroll
        for (int i = 0; i < 4; i++) {
            int id = ptid + i * 128;
            int row = id >> 3, c8 = id & 7;
            uint32_t ad = (uint32_t)(row * 144 + c8 * 16);
            float4 v0 = r[2 * i], v1 = r[2 * i + 1];
            sts128(bb + G1_OFF_B1 + ad, h2u(v0.x, v0.y), h2u(v0.z, v0.w),
                                        h2u(v1.x, v1.y), h2u(v1.z, v1.w));
            float4 u0 = r[8 + 2 * i], u1 = r[8 + 2 * i + 1];
            sts128(bb + G1_OFF_B3 + ad, h2u(u0.x, u0.y), h2u(u0.z, u0.w),
                                        h2u(u1.x, u1.y), h2u(u1.z, u1.w));
        }
        CPA_WAIT0();
    };

    // ---- consumer fragment addresses ----
    int mi = lane >> 3, l8 = lane & 7;
    uint32_t aoff[2], boff[2];
    #pragma unroll
    for (int fm = 0; fm < 2; fm++)
        aoff[fm] = (uint32_t)(((wm * 32 + fm * 16 + 8 * (mi & 1) + l8) * PH + 8 * (mi >> 1)) * 2);
    #pragma unroll
    for (int p = 0; p < 2; p++)
        boff[p] = (uint32_t)(((wn * 32 + p * 16 + 8 * (mi >> 1) + l8) * PH + 8 * (mi & 1)) * 2);

    float acc1[2][4][4], acc3[2][4][4];
    #pragma unroll
    for (int a = 0; a < 2; a++)
        #pragma unroll
        for (int b = 0; b < 4; b++)
            #pragma unroll
            for (int c = 0; c < 4; c++) { acc1[a][b][c] = 0.f; acc3[a][b][c] = 0.f; }

    if (ptid >= 0) produce(0, 0);
    __syncthreads();

    const int NK = H / BK;   // 16
    for (int kc = 0; kc < NK; kc++) {
        int cur = kc & 1;
        if (tid < 256) {
            uint32_t sA  = sb + (uint32_t)cur * G1_STAGE_B;
            uint32_t sB1 = sA + G1_OFF_B1;
            uint32_t sB3 = sA + G1_OFF_B3;
            #pragma unroll
            for (int ks = 0; ks < 4; ks++) {
                uint32_t kb = (uint32_t)ks * 32;
                uint32_t a[2][4];
                ldsm4(a[0][0], a[0][1], a[0][2], a[0][3], sA + aoff[0] + kb);
                ldsm4(a[1][0], a[1][1], a[1][2], a[1][3], sA + aoff[1] + kb);
                uint32_t b1[4][2], b3[4][2];
                ldsm4(b1[0][0], b1[0][1], b1[1][0], b1[1][1], sB1 + boff[0] + kb);
                ldsm4(b1[2][0], b1[2][1], b1[3][0], b1[3][1], sB1 + boff[1] + kb);
                ldsm4(b3[0][0], b3[0][1], b3[1][0], b3[1][1], sB3 + boff[0] + kb);
                ldsm4(b3[2][0], b3[2][1], b3[3][0], b3[3][1], sB3 + boff[1] + kb);
                #pragma unroll
                for (int fm = 0; fm < 2; fm++)
                    #pragma unroll
                    for (int fn = 0; fn < 4; fn++) {
                        mma_f16(acc1[fm][fn], a[fm], b1[fn]);
                        mma_f16(acc3[fm][fn], a[fm], b3[fn]);
                    }
            }
        } else if (kc + 1 < NK) {
            produce(kc + 1, cur ^ 1);
        }
        __syncthreads();
    }

    // ---- epilogue (compute warps): gelu(acc1)*acc3 -> g_act (fp16) ----
    if (tid < 256) {
        __half* actb = g_act + (size_t)e * T * F;
        #pragma unroll
        for (int fm = 0; fm < 2; fm++) {
            int ml = wm * 32 + fm * 16 + g;
            #pragma unroll
            for (int fn = 0; fn < 4; fn++) {
                int col = n0 + wn * 32 + fn * 8 + 2 * t4;
                int ig0 = i0 + ml, ig1 = ig0 + 8;
                if (ig0 < cnt) {
                    float g0 = acc1[fm][fn][0], g1 = acc1[fm][fn][1];
                    __half2 v = __floats2half2_rn(g0 * normcdff(g0) * acc3[fm][fn][0],
                                                  g1 * normcdff(g1) * acc3[fm][fn][1]);
                    *reinterpret_cast<__half2*>(actb + (size_t)ig0 * F + col) = v;
                }
                if (ig1 < cnt) {
                    float g2 = acc1[fm][fn][2], g3 = acc1[fm][fn][3];
                    __half2 v = __floats2half2_rn(g2 * normcdff(g2) * acc3[fm][fn][2],
                                                  g3 * normcdff(g3) * acc3[fm][fn][3]);
                    *reinterpret_cast<__half2*>(actb + (size_t)ig1 * F + col) = v;
                }
            }
        }
    }
}

// ================= gemm2: out[tok] += wgt * (act @ w2^T), warp-specialized =================
// CTA 128m x 128n, BK=64. Warps 0-7 compute (warp 32x64), warps 8-11 produce:
//   A from g_act (fp16 cp.async, 128 rows -> 8 iters), B from fp32 w2 (128 rows -> 8 iters).
#define G2_STAGE_B 36864u
#define G2_OFF_B   18432u
#define G2_SMEM    (2u * G2_STAGE_B)

__global__ __launch_bounds__(NTHREADS, 1) void gemm2_ws(const float* __restrict__ w2,
                                                        float* __restrict__ out) {
    extern __shared__ __half smem[];
    __shared__ int   s_tok[128];
    __shared__ float s_wt[128];

    int e = blockIdx.z;
    int cnt = g_cnt[e];
    int i0 = blockIdx.y * 128;
    if (i0 >= cnt) return;
    int n0 = blockIdx.x * 128;
    int tid = threadIdx.x;
    int wid = tid >> 5, lane = tid & 31;
    int g = lane >> 2, t4 = lane & 3;
    int wm = wid & 3, wn = (wid >> 2) & 1;   // compute-warp tile: m 32*wm, n 64*wn
    int mrows = min(128, cnt - i0);

    if (tid < 128) {
        int i = i0 + tid;
        s_tok[tid] = (i < cnt) ? g_tok[e][i] : -1;
        s_wt[tid]  = (i < cnt) ? g_wt[e][i]  : 0.0f;
    }
    __syncthreads();

    uint32_t sb = smem_u32(smem);
    const __half* Ag = g_act + ((size_t)e * T + i0) * F;
    const float*  Bg = w2 + ((size_t)e * H + n0) * F;

    int ptid = tid - 256;
    auto produce = [&](int kc, int buf) {
        int k0 = kc * BK;
        uint32_t bb = sb + (uint32_t)buf * G2_STAGE_B;
        // A: 128 rows x 8 chunks of 16B (fp16, ragged). 1024 ids / 128 thr = 8 iters.
        #pragma unroll
        for (int i = 0; i < 8; i++) {
            int id = ptid + i * 128;
            int row = id >> 3, c8 = id & 7;
            bool v = row < mrows;
            const __half* src = v ? Ag + (size_t)row * F + k0 + c8 * 8 : Ag;
            cpa16(bb + (uint32_t)(row * 144 + c8 * 16), src, v ? 16u : 0u);
        }
        CPA_COMMIT();
        // B: 128 rows x 8 fp32-chunks of 32B (1024 ids / 128 thr = 8 iters);
        // batch LDGs then cvt+STS
        float4 r[16];
        #pragma unroll
        for (int i = 0; i < 8; i++) {
            int id = ptid + i * 128;
            int row = id >> 3, c8 = id & 7;
            const float* p = Bg + (size_t)row * F + k0 + c8 * 8;
            r[2 * i]     = *reinterpret_cast<const float4*>(p);
            r[2 * i + 1] = *reinterpret_cast<const float4*>(p + 4);
        }
        #pragma unroll
        for (int i = 0; i < 8; i++) {
            int id = ptid + i * 128;
            int row = id >> 3, c8 = id & 7;
            float4 v0 = r[2 * i], v1 = r[2 * i + 1];
            sts128(bb + G2_OFF_B + (uint32_t)(row * 144 + c8 * 16),
                   h2u(v0.x, v0.y), h2u(v0.z, v0.w), h2u(v1.x, v1.y), h2u(v1.z, v1.w));
        }
        CPA_WAIT0();
    };

    int mi = lane >> 3, l8 = lane & 7;
    uint32_t aoff[2], boff[4];
    #pragma unroll
    for (int fm = 0; fm < 2; fm++)
        aoff[fm] = (uint32_t)(((wm * 32 + fm * 16 + 8 * (mi & 1) + l8) * PH + 8 * (mi >> 1)) * 2);
    #pragma unroll
    for (int p = 0; p < 4; p++)
        boff[p] = (uint32_t)(((wn * 64 + p * 16 + 8 * (mi >> 1) + l8) * PH + 8 * (mi & 1)) * 2);

    float acc[2][8][4];
    #pragma unroll
    for (int a = 0; a < 2; a++)
        #pragma unroll
        for (int b = 0; b < 8; b++)
            #pragma unroll
            for (int c = 0; c < 4; c++) acc[a][b][c] = 0.f;

    if (ptid >= 0) produce(0, 0);
    __syncthreads();

    const int NK = F / BK;   // 64
    for (int kc = 0; kc < NK; kc++) {
        int cur = kc & 1;
        if (tid < 256) {
            uint32_t sA = sb + (uint32_t)cur * G2_STAGE_B;
            uint32_t sB = sA + G2_OFF_B;
            #pragma unroll
            for (int ks = 0; ks < 4; ks++) {
                uint32_t kb = (uint32_t)ks * 32;
                uint32_t a[2][4];
                ldsm4(a[0][0], a[0][1], a[0][2], a[0][3], sA + aoff[0] + kb);
                ldsm4(a[1][0], a[1][1], a[1][2], a[1][3], sA + aoff[1] + kb);
                uint32_t b[8][2];
                ldsm4(b[0][0], b[0][1], b[1][0], b[1][1], sB + boff[0] + kb);
                ldsm4(b[2][0], b[2][1], b[3][0], b[3][1], sB + boff[1] + kb);
                ldsm4(b[4][0], b[4][1], b[5][0], b[5][1], sB + boff[2] + kb);
                ldsm4(b[6][0], b[6][1], b[7][0], b[7][1], sB + boff[3] + kb);
                #pragma unroll
                for (int fm = 0; fm < 2; fm++)
                    #pragma unroll
                    for (int fn = 0; fn < 8; fn++)
                        mma_f16(acc[fm][fn], a[fm], b[fn]);
            }
        } else if (kc + 1 < NK) {
            produce(kc + 1, cur ^ 1);
        }
        __syncthreads();
    }

    // ---- epilogue (compute warps): 2 deterministic atomic adds per out element ----
    if (tid < 256) {
        #pragma unroll
        for (int fm = 0; fm < 2; fm++) {
            int ml0 = wm * 32 + fm * 16 + g;
            int ml1 = ml0 + 8;
            int tok0 = s_tok[ml0], tok1 = s_tok[ml1];
            float w0 = s_wt[ml0], w1v = s_wt[ml1];
            #pragma unroll
            for (int fn = 0; fn < 8; fn++) {
                int col = n0 + wn * 64 + fn * 8 + 2 * t4;
                if (tok0 >= 0) {
                    float* o = out + (size_t)tok0 * H + col;
                    atomicAdd(o,     w0 * acc[fm][fn][0]);
                    atomicAdd(o + 1, w0 * acc[fm][fn][1]);
                }
                if (tok1 >= 0) {
                    float* o = out + (size_t)tok1 * H + col;
                    atomicAdd(o,     w1v * acc[fm][fn][2]);
                    atomicAdd(o + 1, w1v * acc[fm][fn][3]);
                }
            }
        }
    }
}

// ---------------- launch ----------------
extern "C" void kernel_launch(void* const* d_in, const int* in_sizes, int n_in,
                              void* d_out, int out_size) {
    const float* hs = (const float*)d_in[0];
    const float* gw = (const float*)d_in[1];
    const float* w1 = (const float*)d_in[2];
    const float* w2 = (const float*)d_in[3];
    const float* w3 = (const float*)d_in[4];
    float* out = (float*)d_out;

    cudaFuncSetAttribute(gemm1_ws, cudaFuncAttributeMaxDynamicSharedMemorySize, G1_SMEM);
    cudaFuncSetAttribute(gemm2_ws, cudaFuncAttributeMaxDynamicSharedMemorySize, G2_SMEM);

    __half* d_hs; cudaGetSymbolAddress((void**)&d_hs, c_hs);

    init_cvt_kernel<<<1024, 256>>>(out, (const float4*)hs, (uint2*)d_hs);
    router_kernel<<<T, 256>>>(hs, gw);
    gemm1_ws<<<dim3(F / 64, T / 128, E), NTHREADS, G1_SMEM>>>(w1, w3);
    gemm2_ws<<<dim3(H / 128, T / 128, E), NTHREADS, G2_SMEM>>>(w2, out);
}

// round 9
// speedup vs baseline: 1.3574x; 1.3574x over previous
#include <cuda_runtime.h>
#include <cuda_fp16.h>
#include <math.h>
#include <stdint.h>

#define T 2048
#define H 1024
#define F 4096
#define E 8

// ---------------- scratch (static device globals; no allocation) ----------------
__device__ int    g_cnt[E];
__device__ int    g_tok[E][T];
__device__ float  g_wt[E][T];
__device__ __half g_act[(size_t)E * T * F];      // fp16 activation scratch
__device__ __half c_hs[(size_t)T * H];           // fp16 copies of inputs
__device__ __half c_w1[(size_t)E * F * H];
__device__ __half c_w3[(size_t)E * F * H];
__device__ __half c_w2[(size_t)E * H * F];

// ================= family-safe PTX helpers =================
__device__ __forceinline__ uint32_t smem_u32(const void* p) {
    uint32_t a;
    asm("{ .reg .u64 t; cvta.to.shared.u64 t, %1; cvt.u32.u64 %0, t; }" : "=r"(a) : "l"(p));
    return a;
}
// d += a * b  (m16n8k16, fp16 inputs, fp32 accum)
__device__ __forceinline__ void mma_f16(float* d, const uint32_t* a, const uint32_t* b) {
    asm volatile(
        "mma.sync.aligned.m16n8k16.row.col.f32.f16.f16.f32 "
        "{%0,%1,%2,%3}, {%4,%5,%6,%7}, {%8,%9}, {%0,%1,%2,%3};"
        : "+f"(d[0]), "+f"(d[1]), "+f"(d[2]), "+f"(d[3])
        : "r"(a[0]), "r"(a[1]), "r"(a[2]), "r"(a[3]), "r"(b[0]), "r"(b[1]));
}
// warp-collective: load 4 8x8 b16 matrices (fragment regs)
__device__ __forceinline__ void ldsm4(uint32_t& r0, uint32_t& r1, uint32_t& r2, uint32_t& r3,
                                      uint32_t addr) {
    asm volatile("ldmatrix.sync.aligned.m8n8.x4.shared.b16 {%0,%1,%2,%3}, [%4];"
                 : "=r"(r0), "=r"(r1), "=r"(r2), "=r"(r3) : "r"(addr));
}
__device__ __forceinline__ void cpa16(uint32_t dst, const void* src, uint32_t sz) {
    asm volatile("cp.async.cg.shared.global [%0], [%1], 16, %2;"
                 :: "r"(dst), "l"(src), "r"(sz) : "memory");
}
#define CPA_COMMIT() asm volatile("cp.async.commit_group;" ::: "memory")
#define CPA_WAIT(n)  asm volatile("cp.async.wait_group %0;" :: "n"(n) : "memory")

__device__ __forceinline__ uint32_t h2u(float x, float y) {
    __half2 h = __floats2half2_rn(x, y);
    return *reinterpret_cast<uint32_t*>(&h);
}

// fp16 SMEM tile pitch: 72 halfs (144B). ldmatrix rows hit banks 4r mod 32 -> conflict-free.
#define PH 72
#define BK 64
#define STAGES 3

// ---------------- init + ALL fp32->fp16 converts, one launch ----------------
__global__ void init_cvt_all(float* __restrict__ out,
                             const float4* __restrict__ hs,
                             const float4* __restrict__ w1,
                             const float4* __restrict__ w3,
                             const float4* __restrict__ w2,
                             uint2* __restrict__ dhs, uint2* __restrict__ dw1,
                             uint2* __restrict__ dw3, uint2* __restrict__ dw2) {
    int idx = blockIdx.x * blockDim.x + threadIdx.x;
    if (idx < E) g_cnt[idx] = 0;
    int stride = gridDim.x * blockDim.x;
    for (int i = idx; i < T * H; i += stride) out[i] = 0.0f;
    for (int i = idx; i < T * H / 4; i += stride) {
        float4 v = hs[i];
        uint2 o; o.x = h2u(v.x, v.y); o.y = h2u(v.z, v.w);
        dhs[i] = o;
    }
    const int NW = E * F * H / 4;
    for (int i = idx; i < NW; i += stride) {
        float4 v = w1[i];
        uint2 o; o.x = h2u(v.x, v.y); o.y = h2u(v.z, v.w);
        dw1[i] = o;
    }
    for (int i = idx; i < NW; i += stride) {
        float4 v = w3[i];
        uint2 o; o.x = h2u(v.x, v.y); o.y = h2u(v.z, v.w);
        dw3[i] = o;
    }
    for (int i = idx; i < NW; i += stride) {
        float4 v = w2[i];
        uint2 o; o.x = h2u(v.x, v.y); o.y = h2u(v.z, v.w);
        dw2[i] = o;
    }
}

// ---------------- router (exact fp32) ----------------
__global__ void router_kernel(const float* __restrict__ hs, const float* __restrict__ gw) {
    int t = blockIdx.x;
    int tid = threadIdx.x;
    int w = tid >> 5, lane = tid & 31;
    const float* hrow = hs + (size_t)t * H;
    const float* grow = gw + (size_t)w * H;
    float s = 0.0f;
    for (int j = lane; j < H; j += 32) s += hrow[j] * grow[j];
    #pragma unroll
    for (int o = 16; o; o >>= 1) s += __shfl_xor_sync(0xffffffffu, s, o);
    __shared__ float s_logit[E];
    if (lane == 0) s_logit[w] = s;
    __syncthreads();
    if (tid == 0) {
        float l[E], m = -1e30f;
        #pragma unroll
        for (int e = 0; e < E; e++) {
            l[e] = 30.0f * tanhf(s_logit[e] * (1.0f / 30.0f));
            m = fmaxf(m, l[e]);
        }
        float p[E], sum = 0.0f;
        #pragma unroll
        for (int e = 0; e < E; e++) { p[e] = expf(l[e] - m); sum += p[e]; }
        float inv = 1.0f / sum;
        #pragma unroll
        for (int e = 0; e < E; e++) p[e] *= inv;
        int e1 = 0;
        #pragma unroll
        for (int e = 1; e < E; e++) if (p[e] > p[e1]) e1 = e;
        int e2 = (e1 == 0) ? 1 : 0;
        #pragma unroll
        for (int e = 0; e < E; e++) if (e != e1 && p[e] > p[e2]) e2 = e;
        int pos1 = atomicAdd(&g_cnt[e1], 1);
        g_tok[e1][pos1] = t; g_wt[e1][pos1] = p[e1];
        int pos2 = atomicAdd(&g_cnt[e2], 1);
        g_tok[e2][pos2] = t; g_wt[e2][pos2] = p[e2];
    }
}

// ================= gemm1: act = gelu(h@w1^T) * (h@w3^T), fp16 mma =================
// CTA 128m x 64n, BK=64, 8 warps (warp 32x32), 3-stage cp.async, ldmatrix frags.
// __launch_bounds__(256, 2): cap regs at 128 so 2 CTAs co-reside (221KB smem fits).
#define G1_STAGE_B 36864u
#define G1_OFF_B1  18432u
#define G1_OFF_B3  27648u
#define G1_SMEM    (STAGES * G1_STAGE_B)

__global__ __launch_bounds__(256, 2) void gemm1_mma(const float* __restrict__ dummy) {
    extern __shared__ __half smem[];
    __shared__ int s_tok[128];

    int e = blockIdx.z;
    int cnt = g_cnt[e];
    int i0 = blockIdx.y * 128;
    if (i0 >= cnt) return;
    int n0 = blockIdx.x * 64;
    int tid = threadIdx.x;
    int wid = tid >> 5, lane = tid & 31;
    int g = lane >> 2, t4 = lane & 3;
    int wm = wid & 3, wn = wid >> 2;       // warp tile: m 32*wm, n 32*wn

    if (tid < 128) {
        int i = i0 + tid;
        s_tok[tid] = (i < cnt) ? g_tok[e][i] : -1;
    }
    __syncthreads();

    uint32_t sb = smem_u32(smem);

    // ldmatrix per-lane byte offsets within a stage
    int mi = lane >> 3, l8 = lane & 7;
    uint32_t aoff[2], boff[2];
    #pragma unroll
    for (int fm = 0; fm < 2; fm++)   // A: row-half = mi&1, k-half = mi>>1
        aoff[fm] = (uint32_t)(((wm * 32 + fm * 16 + 8 * (mi & 1) + l8) * PH + 8 * (mi >> 1)) * 2);
    #pragma unroll
    for (int p = 0; p < 2; p++)      // B pair: n-group = mi>>1, k-half = mi&1
        boff[p] = (uint32_t)(((wn * 32 + p * 16 + 8 * (mi >> 1) + l8) * PH + 8 * (mi & 1)) * 2);

    auto stage = [&](int kc, int buf) {
        int k0 = kc * BK;
        uint32_t bb = sb + (uint32_t)buf * G1_STAGE_B;
        const __half* w1g = c_w1 + ((size_t)e * F + n0) * H;
        const __half* w3g = c_w3 + ((size_t)e * F + n0) * H;
        #pragma unroll
        for (int i = 0; i < 4; i++) {              // A gathered: 128 rows x 8 chunks
            int id = tid + i * 256;
            int row = id >> 3, c8 = id & 7;
            int tok = s_tok[row];
            const __half* src = (tok >= 0) ? c_hs + (size_t)tok * H + k0 + c8 * 8 : c_hs;
            cpa16(bb + (uint32_t)(row * 144 + c8 * 16), src, tok >= 0 ? 16u : 0u);
        }
        #pragma unroll
        for (int i = 0; i < 2; i++) {              // B1: 64 rows x 8 chunks
            int id = tid + i * 256;
            int row = id >> 3, c8 = id & 7;
            cpa16(bb + G1_OFF_B1 + (uint32_t)(row * 144 + c8 * 16),
                  w1g + (size_t)row * H + k0 + c8 * 8, 16u);
        }
        #pragma unroll
        for (int i = 0; i < 2; i++) {              // B3
            int id = tid + i * 256;
            int row = id >> 3, c8 = id & 7;
            cpa16(bb + G1_OFF_B3 + (uint32_t)(row * 144 + c8 * 16),
                  w3g + (size_t)row * H + k0 + c8 * 8, 16u);
        }
    };

    float acc1[2][4][4], acc3[2][4][4];
    #pragma unroll
    for (int a = 0; a < 2; a++)
        #pragma unroll
        for (int b = 0; b < 4; b++)
            #pragma unroll
            for (int c = 0; c < 4; c++) { acc1[a][b][c] = 0.f; acc3[a][b][c] = 0.f; }

    stage(0, 0); CPA_COMMIT();
    stage(1, 1); CPA_COMMIT();

    const int NK = H / BK;   // 16
    for (int kc = 0; kc < NK; kc++) {
        int cur = kc % STAGES;
        CPA_WAIT(1);
        __syncthreads();
        if (kc + 2 < NK) stage(kc + 2, (kc + 2) % STAGES);
        CPA_COMMIT();

        uint32_t sA  = sb + (uint32_t)cur * G1_STAGE_B;
        uint32_t sB1 = sA + G1_OFF_B1;
        uint32_t sB3 = sA + G1_OFF_B3;

        #pragma unroll
        for (int ks = 0; ks < 4; ks++) {           // 4 x k16
            uint32_t kb = (uint32_t)ks * 32;       // 16 halfs
            uint32_t a[2][4];
            ldsm4(a[0][0], a[0][1], a[0][2], a[0][3], sA + aoff[0] + kb);
            ldsm4(a[1][0], a[1][1], a[1][2], a[1][3], sA + aoff[1] + kb);
            uint32_t b1[4][2], b3[4][2];
            ldsm4(b1[0][0], b1[0][1], b1[1][0], b1[1][1], sB1 + boff[0] + kb);
            ldsm4(b1[2][0], b1[2][1], b1[3][0], b1[3][1], sB1 + boff[1] + kb);
            ldsm4(b3[0][0], b3[0][1], b3[1][0], b3[1][1], sB3 + boff[0] + kb);
            ldsm4(b3[2][0], b3[2][1], b3[3][0], b3[3][1], sB3 + boff[1] + kb);
            #pragma unroll
            for (int fm = 0; fm < 2; fm++)
                #pragma unroll
                for (int fn = 0; fn < 4; fn++) {
                    mma_f16(acc1[fm][fn], a[fm], b1[fn]);
                    mma_f16(acc3[fm][fn], a[fm], b3[fn]);
                }
        }
    }

    // ---- epilogue: gelu(acc1)*acc3 -> g_act (fp16) ----
    __half* actb = g_act + (size_t)e * T * F;
    #pragma unroll
    for (int fm = 0; fm < 2; fm++) {
        int ml = wm * 32 + fm * 16 + g;
        #pragma unroll
        for (int fn = 0; fn < 4; fn++) {
            int col = n0 + wn * 32 + fn * 8 + 2 * t4;
            int ig0 = i0 + ml, ig1 = ig0 + 8;
            if (ig0 < cnt) {
                float g0 = acc1[fm][fn][0], g1 = acc1[fm][fn][1];
                __half2 v = __floats2half2_rn(g0 * normcdff(g0) * acc3[fm][fn][0],
                                              g1 * normcdff(g1) * acc3[fm][fn][1]);
                *reinterpret_cast<__half2*>(actb + (size_t)ig0 * F + col) = v;
            }
            if (ig1 < cnt) {
                float g2 = acc1[fm][fn][2], g3 = acc1[fm][fn][3];
                __half2 v = __floats2half2_rn(g2 * normcdff(g2) * acc3[fm][fn][2],
                                              g3 * normcdff(g3) * acc3[fm][fn][3]);
                *reinterpret_cast<__half2*>(actb + (size_t)ig1 * F + col) = v;
            }
        }
    }
}

// ================= gemm2: out[tok] += wgt * (act @ w2^T), fp16 mma =================
// CTA 128m x 128n, BK=64, 8 warps (warp 32x64), 3-stage cp.async, ldmatrix frags.
#define G2_STAGE_B 36864u
#define G2_OFF_B   18432u
#define G2_SMEM    (STAGES * G2_STAGE_B)

__global__ __launch_bounds__(256, 2) void gemm2_mma(float* __restrict__ out) {
    extern __shared__ __half smem[];
    __shared__ int   s_tok[128];
    __shared__ float s_wt[128];

    int e = blockIdx.z;
    int cnt = g_cnt[e];
    int i0 = blockIdx.y * 128;
    if (i0 >= cnt) return;
    int n0 = blockIdx.x * 128;
    int tid = threadIdx.x;
    int wid = tid >> 5, lane = tid & 31;
    int g = lane >> 2, t4 = lane & 3;
    int wm = wid & 3, wn = wid >> 2;       // warp tile: m 32*wm, n 64*wn
    int mrows = min(128, cnt - i0);

    if (tid < 128) {
        int i = i0 + tid;
        s_tok[tid] = (i < cnt) ? g_tok[e][i] : -1;
        s_wt[tid]  = (i < cnt) ? g_wt[e][i]  : 0.0f;
    }
    __syncthreads();

    uint32_t sb = smem_u32(smem);

    int mi = lane >> 3, l8 = lane & 7;
    uint32_t aoff[2], boff[4];
    #pragma unroll
    for (int fm = 0; fm < 2; fm++)
        aoff[fm] = (uint32_t)(((wm * 32 + fm * 16 + 8 * (mi & 1) + l8) * PH + 8 * (mi >> 1)) * 2);
    #pragma unroll
    for (int p = 0; p < 4; p++)
        boff[p] = (uint32_t)(((wn * 64 + p * 16 + 8 * (mi >> 1) + l8) * PH + 8 * (mi & 1)) * 2);

    const __half* Ag = g_act + ((size_t)e * T + i0) * F;
    const __half* Bg = c_w2 + ((size_t)e * H + n0) * F;

    auto stage = [&](int kc, int buf) {
        int k0 = kc * BK;
        uint32_t bb = sb + (uint32_t)buf * G2_STAGE_B;
        #pragma unroll
        for (int i = 0; i < 4; i++) {              // A (ragged)
            int id = tid + i * 256;
            int row = id >> 3, c8 = id & 7;
            bool v = row < mrows;
            const __half* src = v ? Ag + (size_t)row * F + k0 + c8 * 8 : Ag;
            cpa16(bb + (uint32_t)(row * 144 + c8 * 16), src, v ? 16u : 0u);
        }
        #pragma unroll
        for (int i = 0; i < 4; i++) {              // B
            int id = tid + i * 256;
            int row = id >> 3, c8 = id & 7;
            cpa16(bb + G2_OFF_B + (uint32_t)(row * 144 + c8 * 16),
                  Bg + (size_t)row * F + k0 + c8 * 8, 16u);
        }
    };

    float acc[2][8][4];
    #pragma unroll
    for (int a = 0; a < 2; a++)
        #pragma unroll
        for (int b = 0; b < 8; b++)
            #pragma unroll
            for (int c = 0; c < 4; c++) acc[a][b][c] = 0.f;

    stage(0, 0); CPA_COMMIT();
    stage(1, 1); CPA_COMMIT();

    const int NK = F / BK;   // 64
    for (int kc = 0; kc < NK; kc++) {
        int cur = kc % STAGES;
        CPA_WAIT(1);
        __syncthreads();
        if (kc + 2 < NK) stage(kc + 2, (kc + 2) % STAGES);
        CPA_COMMIT();

        uint32_t sA = sb + (uint32_t)cur * G2_STAGE_B;
        uint32_t sB = sA + G2_OFF_B;

        #pragma unroll
        for (int ks = 0; ks < 4; ks++) {
            uint32_t kb = (uint32_t)ks * 32;
            uint32_t a[2][4];
            ldsm4(a[0][0], a[0][1], a[0][2], a[0][3], sA + aoff[0] + kb);
            ldsm4(a[1][0], a[1][1], a[1][2], a[1][3], sA + aoff[1] + kb);
            uint32_t b[8][2];
            ldsm4(b[0][0], b[0][1], b[1][0], b[1][1], sB + boff[0] + kb);
            ldsm4(b[2][0], b[2][1], b[3][0], b[3][1], sB + boff[1] + kb);
            ldsm4(b[4][0], b[4][1], b[5][0], b[5][1], sB + boff[2] + kb);
            ldsm4(b[6][0], b[6][1], b[7][0], b[7][1], sB + boff[3] + kb);
            #pragma unroll
            for (int fm = 0; fm < 2; fm++)
                #pragma unroll
                for (int fn = 0; fn < 8; fn++)
                    mma_f16(acc[fm][fn], a[fm], b[fn]);
        }
    }

    // ---- epilogue: 2 deterministic atomic adds per out element ----
    #pragma unroll
    for (int fm = 0; fm < 2; fm++) {
        int ml0 = wm * 32 + fm * 16 + g;
        int ml1 = ml0 + 8;
        int tok0 = s_tok[ml0], tok1 = s_tok[ml1];
        float w0 = s_wt[ml0], w1v = s_wt[ml1];
        #pragma unroll
        for (int fn = 0; fn < 8; fn++) {
            int col = n0 + wn * 64 + fn * 8 + 2 * t4;
            if (tok0 >= 0) {
                float* o = out + (size_t)tok0 * H + col;
                atomicAdd(o,     w0 * acc[fm][fn][0]);
                atomicAdd(o + 1, w0 * acc[fm][fn][1]);
            }
            if (tok1 >= 0) {
                float* o = out + (size_t)tok1 * H + col;
                atomicAdd(o,     w1v * acc[fm][fn][2]);
                atomicAdd(o + 1, w1v * acc[fm][fn][3]);
            }
        }
    }
}

// ---------------- launch ----------------
extern "C" void kernel_launch(void* const* d_in, const int* in_sizes, int n_in,
                              void* d_out, int out_size) {
    const float* hs = (const float*)d_in[0];
    const float* gw = (const float*)d_in[1];
    const float* w1 = (const float*)d_in[2];
    const float* w2 = (const float*)d_in[3];
    const float* w3 = (const float*)d_in[4];
    float* out = (float*)d_out;

    cudaFuncSetAttribute(gemm1_mma, cudaFuncAttributeMaxDynamicSharedMemorySize, G1_SMEM);
    cudaFuncSetAttribute(gemm2_mma, cudaFuncAttributeMaxDynamicSharedMemorySize, G2_SMEM);

    __half* d_hs; cudaGetSymbolAddress((void**)&d_hs, c_hs);
    __half* d_w1; cudaGetSymbolAddress((void**)&d_w1, c_w1);
    __half* d_w2; cudaGetSymbolAddress((void**)&d_w2, c_w2);
    __half* d_w3; cudaGetSymbolAddress((void**)&d_w3, c_w3);

    init_cvt_all<<<4096, 256>>>(out, (const float4*)hs, (const float4*)w1,
                                (const float4*)w3, (const float4*)w2,
                                (uint2*)d_hs, (uint2*)d_w1, (uint2*)d_w3, (uint2*)d_w2);
    router_kernel<<<T, 256>>>(hs, gw);
    gemm1_mma<<<dim3(F / 64, T / 128, E), 256, G1_SMEM>>>(hs);
    gemm2_mma<<<dim3(H / 128, T / 128, E), 256, G2_SMEM>>>(out);
}

// round 11
// speedup vs baseline: 1.3767x; 1.0142x over previous
#include <cuda_runtime.h>
#include <cuda_fp16.h>
#include <math.h>
#include <stdint.h>

#define T 2048
#define H 1024
#define F 4096
#define E 8

// ---------------- scratch (static device globals; no allocation) ----------------
__device__ int    g_cnt[E];
__device__ int    g_tok[E][T];
__device__ float  g_wt[E][T];
__device__ __half g_act[(size_t)E * T * F];      // fp16 activation scratch
__device__ __half c_hs[(size_t)T * H];           // fp16 copies of inputs
__device__ __half c_w1[(size_t)E * F * H];
__device__ __half c_w3[(size_t)E * F * H];
__device__ __half c_w2[(size_t)E * H * F];

// ================= family-safe PTX helpers =================
__device__ __forceinline__ uint32_t smem_u32(const void* p) {
    uint32_t a;
    asm("{ .reg .u64 t; cvta.to.shared.u64 t, %1; cvt.u32.u64 %0, t; }" : "=r"(a) : "l"(p));
    return a;
}
// d += a * b  (m16n8k16, fp16 inputs, fp32 accum)
__device__ __forceinline__ void mma_f16(float* d, const uint32_t* a, const uint32_t* b) {
    asm volatile(
        "mma.sync.aligned.m16n8k16.row.col.f32.f16.f16.f32 "
        "{%0,%1,%2,%3}, {%4,%5,%6,%7}, {%8,%9}, {%0,%1,%2,%3};"
        : "+f"(d[0]), "+f"(d[1]), "+f"(d[2]), "+f"(d[3])
        : "r"(a[0]), "r"(a[1]), "r"(a[2]), "r"(a[3]), "r"(b[0]), "r"(b[1]));
}
// warp-collective: load 4 8x8 b16 matrices (fragment regs)
__device__ __forceinline__ void ldsm4(uint32_t& r0, uint32_t& r1, uint32_t& r2, uint32_t& r3,
                                      uint32_t addr) {
    asm volatile("ldmatrix.sync.aligned.m8n8.x4.shared.b16 {%0,%1,%2,%3}, [%4];"
                 : "=r"(r0), "=r"(r1), "=r"(r2), "=r"(r3) : "r"(addr));
}
__device__ __forceinline__ void cpa16(uint32_t dst, const void* src, uint32_t sz) {
    asm volatile("cp.async.cg.shared.global [%0], [%1], 16, %2;"
                 :: "r"(dst), "l"(src), "r"(sz) : "memory");
}
#define CPA_COMMIT() asm volatile("cp.async.commit_group;" ::: "memory")
#define CPA_WAIT(n)  asm volatile("cp.async.wait_group %0;" :: "n"(n) : "memory")

__device__ __forceinline__ uint32_t h2u(float x, float y) {
    __half2 h = __floats2half2_rn(x, y);
    return *reinterpret_cast<uint32_t*>(&h);
}

// fp16 SMEM tile pitch: 72 halfs (144B). ldmatrix rows hit banks 4r mod 32 -> conflict-free.
#define PH 72
#define BK 64
#define STAGES 3

// ---------------- tiny init: zero per-expert counters (must precede router atomics) ----------------
__global__ void init8_kernel() {
    if (threadIdx.x < E) g_cnt[threadIdx.x] = 0;
}

// ---------------- router (exact fp32) + hs/w1/w3 cvt + out zero, one launch ----------------
__global__ __launch_bounds__(256) void router_cvt_kernel(
    const float* __restrict__ hs, const float* __restrict__ gw,
    const float4* __restrict__ w1f, const float4* __restrict__ w3f,
    float* __restrict__ out,
    const float4* __restrict__ hsf) {
    int t = blockIdx.x;
    int tid = threadIdx.x;
    int w = tid >> 5, lane = tid & 31;
    const float* hrow = hs + (size_t)t * H;
    const float* grow = gw + (size_t)w * H;
    float s = 0.0f;
    for (int j = lane; j < H; j += 32) s += hrow[j] * grow[j];
    #pragma unroll
    for (int o = 16; o; o >>= 1) s += __shfl_xor_sync(0xffffffffu, s, o);
    __shared__ float s_logit[E];
    if (lane == 0) s_logit[w] = s;
    __syncthreads();
    if (tid == 0) {
        float l[E], m = -1e30f;
        #pragma unroll
        for (int e = 0; e < E; e++) {
            l[e] = 30.0f * tanhf(s_logit[e] * (1.0f / 30.0f));
            m = fmaxf(m, l[e]);
        }
        float p[E], sum = 0.0f;
        #pragma unroll
        for (int e = 0; e < E; e++) { p[e] = expf(l[e] - m); sum += p[e]; }
        float inv = 1.0f / sum;
        #pragma unroll
        for (int e = 0; e < E; e++) p[e] *= inv;
        int e1 = 0;
        #pragma unroll
        for (int e = 1; e < E; e++) if (p[e] > p[e1]) e1 = e;
        int e2 = (e1 == 0) ? 1 : 0;
        #pragma unroll
        for (int e = 0; e < E; e++) if (e != e1 && p[e] > p[e2]) e2 = e;
        int pos1 = atomicAdd(&g_cnt[e1], 1);
        g_tok[e1][pos1] = t; g_wt[e1][pos1] = p[e1];
        int pos2 = atomicAdd(&g_cnt[e2], 1);
        g_tok[e2][pos2] = t; g_wt[e2][pos2] = p[e2];
    }

    // ---- bulk work (grid-strided over 2048*256 threads) ----
    int gid = t * 256 + tid;
    const int GS = T * 256;                       // 524288 threads
    // out zero: 2M floats -> 4 per thread (float4)
    {
        float4* o4 = (float4*)out;
        for (int i = gid; i < T * H / 4; i += GS) o4[i] = make_float4(0.f, 0.f, 0.f, 0.f);
    }
    // hs cvt: 524288 float4 -> 1 per thread
    {
        uint2* dst = (uint2*)c_hs;
        for (int i = gid; i < T * H / 4; i += GS) {
            float4 v = hsf[i];
            uint2 o; o.x = h2u(v.x, v.y); o.y = h2u(v.z, v.w);
            dst[i] = o;
        }
    }
    // w1 + w3 cvt: 8.4M float4 each -> 16 per thread
    {
        const int NW = E * F * H / 4;
        uint2* d1 = (uint2*)c_w1;
        uint2* d3 = (uint2*)c_w3;
        for (int i = gid; i < NW; i += GS) {
            float4 v = w1f[i];
            uint2 o; o.x = h2u(v.x, v.y); o.y = h2u(v.z, v.w);
            d1[i] = o;
        }
        for (int i = gid; i < NW; i += GS) {
            float4 v = w3f[i];
            uint2 o; o.x = h2u(v.x, v.y); o.y = h2u(v.z, v.w);
            d3[i] = o;
        }
    }
}

// ================= gemm1: act = gelu(h@w1^T) * (h@w3^T), fp16 mma =================
// CTA 128m x 64n, BK=64, 8 warps (warp 32x32), 3-stage cp.async, ldmatrix frags.
// Every CTA (incl. empty m-tiles) also converts its 1024-float4 slice of w2 (for gemm2).
#define G1_STAGE_B 36864u
#define G1_OFF_B1  18432u
#define G1_OFF_B3  27648u
#define G1_SMEM    (STAGES * G1_STAGE_B)

__global__ __launch_bounds__(256, 2) void gemm1_mma(const float4* __restrict__ w2f) {
    extern __shared__ __half smem[];
    __shared__ int s_tok[128];

    int tid = threadIdx.x;

    // ---- w2 fp32->fp16 cvt slice: 8192 CTAs x 1024 float4 = E*H*F/4 exactly ----
    {
        int cta = blockIdx.x + gridDim.x * (blockIdx.y + gridDim.y * blockIdx.z);
        uint2* dst = (uint2*)c_w2;
        size_t base = (size_t)cta * 1024;
        #pragma unroll
        for (int i = 0; i < 4; i++) {
            size_t idx = base + i * 256 + tid;
            float4 v = w2f[idx];
            uint2 o; o.x = h2u(v.x, v.y); o.y = h2u(v.z, v.w);
            dst[idx] = o;
        }
    }

    int e = blockIdx.z;
    int cnt = g_cnt[e];
    int i0 = blockIdx.y * 128;
    if (i0 >= cnt) return;
    int n0 = blockIdx.x * 64;
    int wid = tid >> 5, lane = tid & 31;
    int g = lane >> 2, t4 = lane & 3;
    int wm = wid & 3, wn = wid >> 2;       // warp tile: m 32*wm, n 32*wn

    if (tid < 128) {
        int i = i0 + tid;
        s_tok[tid] = (i < cnt) ? g_tok[e][i] : -1;
    }
    __syncthreads();

    uint32_t sb = smem_u32(smem);

    // ldmatrix per-lane byte offsets within a stage
    int mi = lane >> 3, l8 = lane & 7;
    uint32_t aoff[2], boff[2];
    #pragma unroll
    for (int fm = 0; fm < 2; fm++)   // A: row-half = mi&1, k-half = mi>>1
        aoff[fm] = (uint32_t)(((wm * 32 + fm * 16 + 8 * (mi & 1) + l8) * PH + 8 * (mi >> 1)) * 2);
    #pragma unroll
    for (int p = 0; p < 2; p++)      // B pair: n-group = mi>>1, k-half = mi&1
        boff[p] = (uint32_t)(((wn * 32 + p * 16 + 8 * (mi >> 1) + l8) * PH + 8 * (mi & 1)) * 2);

    auto stage = [&](int kc, int buf) {
        int k0 = kc * BK;
        uint32_t bb = sb + (uint32_t)buf * G1_STAGE_B;
        const __half* w1g = c_w1 + ((size_t)e * F + n0) * H;
        const __half* w3g = c_w3 + ((size_t)e * F + n0) * H;
        #pragma unroll
        for (int i = 0; i < 4; i++) {              // A gathered: 128 rows x 8 chunks
            int id = tid + i * 256;
            int row = id >> 3, c8 = id & 7;
            int tok = s_tok[row];
            const __half* src = (tok >= 0) ? c_hs + (size_t)tok * H + k0 + c8 * 8 : c_hs;
            cpa16(bb + (uint32_t)(row * 144 + c8 * 16), src, tok >= 0 ? 16u : 0u);
        }
        #pragma unroll
        for (int i = 0; i < 2; i++) {              // B1: 64 rows x 8 chunks
            int id = tid + i * 256;
            int row = id >> 3, c8 = id & 7;
            cpa16(bb + G1_OFF_B1 + (uint32_t)(row * 144 + c8 * 16),
                  w1g + (size_t)row * H + k0 + c8 * 8, 16u);
        }
        #pragma unroll
        for (int i = 0; i < 2; i++) {              // B3
            int id = tid + i * 256;
            int row = id >> 3, c8 = id & 7;
            cpa16(bb + G1_OFF_B3 + (uint32_t)(row * 144 + c8 * 16),
                  w3g + (size_t)row * H + k0 + c8 * 8, 16u);
        }
    };

    float acc1[2][4][4], acc3[2][4][4];
    #pragma unroll
    for (int a = 0; a < 2; a++)
        #pragma unroll
        for (int b = 0; b < 4; b++)
            #pragma unroll
            for (int c = 0; c < 4; c++) { acc1[a][b][c] = 0.f; acc3[a][b][c] = 0.f; }

    stage(0, 0); CPA_COMMIT();
    stage(1, 1); CPA_COMMIT();

    const int NK = H / BK;   // 16
    for (int kc = 0; kc < NK; kc++) {
        int cur = kc % STAGES;
        CPA_WAIT(1);
        __syncthreads();
        if (kc + 2 < NK) stage(kc + 2, (kc + 2) % STAGES);
        CPA_COMMIT();

        uint32_t sA  = sb + (uint32_t)cur * G1_STAGE_B;
        uint32_t sB1 = sA + G1_OFF_B1;
        uint32_t sB3 = sA + G1_OFF_B3;

        #pragma unroll
        for (int ks = 0; ks < 4; ks++) {           // 4 x k16
            uint32_t kb = (uint32_t)ks * 32;       // 16 halfs
            uint32_t a[2][4];
            ldsm4(a[0][0], a[0][1], a[0][2], a[0][3], sA + aoff[0] + kb);
            ldsm4(a[1][0], a[1][1], a[1][2], a[1][3], sA + aoff[1] + kb);
            uint32_t b1[4][2], b3[4][2];
            ldsm4(b1[0][0], b1[0][1], b1[1][0], b1[1][1], sB1 + boff[0] + kb);
            ldsm4(b1[2][0], b1[2][1], b1[3][0], b1[3][1], sB1 + boff[1] + kb);
            ldsm4(b3[0][0], b3[0][1], b3[1][0], b3[1][1], sB3 + boff[0] + kb);
            ldsm4(b3[2][0], b3[2][1], b3[3][0], b3[3][1], sB3 + boff[1] + kb);
            #pragma unroll
            for (int fm = 0; fm < 2; fm++)
                #pragma unroll
                for (int fn = 0; fn < 4; fn++) {
                    mma_f16(acc1[fm][fn], a[fm], b1[fn]);
                    mma_f16(acc3[fm][fn], a[fm], b3[fn]);
                }
        }
    }

    // ---- epilogue: gelu(acc1)*acc3 -> g_act (fp16) ----
    __half* actb = g_act + (size_t)e * T * F;
    #pragma unroll
    for (int fm = 0; fm < 2; fm++) {
        int ml = wm * 32 + fm * 16 + g;
        #pragma unroll
        for (int fn = 0; fn < 4; fn++) {
            int col = n0 + wn * 32 + fn * 8 + 2 * t4;
            int ig0 = i0 + ml, ig1 = ig0 + 8;
            if (ig0 < cnt) {
                float g0 = acc1[fm][fn][0], g1 = acc1[fm][fn][1];
                __half2 v = __floats2half2_rn(g0 * normcdff(g0) * acc3[fm][fn][0],
                                              g1 * normcdff(g1) * acc3[fm][fn][1]);
                *reinterpret_cast<__half2*>(actb + (size_t)ig0 * F + col) = v;
            }
            if (ig1 < cnt) {
                float g2 = acc1[fm][fn][2], g3 = acc1[fm][fn][3];
                __half2 v = __floats2half2_rn(g2 * normcdff(g2) * acc3[fm][fn][2],
                                              g3 * normcdff(g3) * acc3[fm][fn][3]);
                *reinterpret_cast<__half2*>(actb + (size_t)ig1 * F + col) = v;
            }
        }
    }
}

// ================= gemm2: out[tok] += wgt * (act @ w2^T), fp16 mma =================
// CTA 128m x 128n, BK=64, 8 warps (warp 32x64), 3-stage cp.async, ldmatrix frags.
#define G2_STAGE_B 36864u
#define G2_OFF_B   18432u
#define G2_SMEM    (STAGES * G2_STAGE_B)

__global__ __launch_bounds__(256, 2) void gemm2_mma(float* __restrict__ out) {
    extern __shared__ __half smem[];
    __shared__ int   s_tok[128];
    __shared__ float s_wt[128];

    int e = blockIdx.z;
    int cnt = g_cnt[e];
    int i0 = blockIdx.y * 128;
    if (i0 >= cnt) return;
    int n0 = blockIdx.x * 128;
    int tid = threadIdx.x;
    int wid = tid >> 5, lane = tid & 31;
    int g = lane >> 2, t4 = lane & 3;
    int wm = wid & 3, wn = wid >> 2;       // warp tile: m 32*wm, n 64*wn
    int mrows = min(128, cnt - i0);

    if (tid < 128) {
        int i = i0 + tid;
        s_tok[tid] = (i < cnt) ? g_tok[e][i] : -1;
        s_wt[tid]  = (i < cnt) ? g_wt[e][i]  : 0.0f;
    }
    __syncthreads();

    uint32_t sb = smem_u32(smem);

    int mi = lane >> 3, l8 = lane & 7;
    uint32_t aoff[2], boff[4];
    #pragma unroll
    for (int fm = 0; fm < 2; fm++)
        aoff[fm] = (uint32_t)(((wm * 32 + fm * 16 + 8 * (mi & 1) + l8) * PH + 8 * (mi >> 1)) * 2);
    #pragma unroll
    for (int p = 0; p < 4; p++)
        boff[p] = (uint32_t)(((wn * 64 + p * 16 + 8 * (mi >> 1) + l8) * PH + 8 * (mi & 1)) * 2);

    const __half* Ag = g_act + ((size_t)e * T + i0) * F;
    const __half* Bg = c_w2 + ((size_t)e * H + n0) * F;

    auto stage = [&](int kc, int buf) {
        int k0 = kc * BK;
        uint32_t bb = sb + (uint32_t)buf * G2_STAGE_B;
        #pragma unroll
        for (int i = 0; i < 4; i++) {              // A (ragged)
            int id = tid + i * 256;
            int row = id >> 3, c8 = id & 7;
            bool v = row < mrows;
            const __half* src = v ? Ag + (size_t)row * F + k0 + c8 * 8 : Ag;
            cpa16(bb + (uint32_t)(row * 144 + c8 * 16), src, v ? 16u : 0u);
        }
        #pragma unroll
        for (int i = 0; i < 4; i++) {              // B
            int id = tid + i * 256;
            int row = id >> 3, c8 = id & 7;
            cpa16(bb + G2_OFF_B + (uint32_t)(row * 144 + c8 * 16),
                  Bg + (size_t)row * F + k0 + c8 * 8, 16u);
        }
    };

    float acc[2][8][4];
    #pragma unroll
    for (int a = 0; a < 2; a++)
        #pragma unroll
        for (int b = 0; b < 8; b++)
            #pragma unroll
            for (int c = 0; c < 4; c++) acc[a][b][c] = 0.f;

    stage(0, 0); CPA_COMMIT();
    stage(1, 1); CPA_COMMIT();

    const int NK = F / BK;   // 64
    for (int kc = 0; kc < NK; kc++) {
        int cur = kc % STAGES;
        CPA_WAIT(1);
        __syncthreads();
        if (kc + 2 < NK) stage(kc + 2, (kc + 2) % STAGES);
        CPA_COMMIT();

        uint32_t sA = sb + (uint32_t)cur * G2_STAGE_B;
        uint32_t sB = sA + G2_OFF_B;

        #pragma unroll
        for (int ks = 0; ks < 4; ks++) {
            uint32_t kb = (uint32_t)ks * 32;
            uint32_t a[2][4];
            ldsm4(a[0][0], a[0][1], a[0][2], a[0][3], sA + aoff[0] + kb);
            ldsm4(a[1][0], a[1][1], a[1][2], a[1][3], sA + aoff[1] + kb);
            uint32_t b[8][2];
            ldsm4(b[0][0], b[0][1], b[1][0], b[1][1], sB + boff[0] + kb);
            ldsm4(b[2][0], b[2][1], b[3][0], b[3][1], sB + boff[1] + kb);
            ldsm4(b[4][0], b[4][1], b[5][0], b[5][1], sB + boff[2] + kb);
            ldsm4(b[6][0], b[6][1], b[7][0], b[7][1], sB + boff[3] + kb);
            #pragma unroll
            for (int fm = 0; fm < 2; fm++)
                #pragma unroll
                for (int fn = 0; fn < 8; fn++)
                    mma_f16(acc[fm][fn], a[fm], b[fn]);
        }
    }

    // ---- epilogue: 2 deterministic atomic adds per out element ----
    #pragma unroll
    for (int fm = 0; fm < 2; fm++) {
        int ml0 = wm * 32 + fm * 16 + g;
        int ml1 = ml0 + 8;
        int tok0 = s_tok[ml0], tok1 = s_tok[ml1];
        float w0 = s_wt[ml0], w1v = s_wt[ml1];
        #pragma unroll
        for (int fn = 0; fn < 8; fn++) {
            int col = n0 + wn * 64 + fn * 8 + 2 * t4;
            if (tok0 >= 0) {
                float* o = out + (size_t)tok0 * H + col;
                atomicAdd(o,     w0 * acc[fm][fn][0]);
                atomicAdd(o + 1, w0 * acc[fm][fn][1]);
            }
            if (tok1 >= 0) {
                float* o = out + (size_t)tok1 * H + col;
                atomicAdd(o,     w1v * acc[fm][fn][2]);
                atomicAdd(o + 1, w1v * acc[fm][fn][3]);
            }
        }
    }
}

// ---------------- launch ----------------
extern "C" void kernel_launch(void* const* d_in, const int* in_sizes, int n_in,
                              void* d_out, int out_size) {
    const float* hs = (const float*)d_in[0];
    const float* gw = (const float*)d_in[1];
    const float* w1 = (const float*)d_in[2];
    const float* w2 = (const float*)d_in[3];
    const float* w3 = (const float*)d_in[4];
    float* out = (float*)d_out;

    cudaFuncSetAttribute(gemm1_mma, cudaFuncAttributeMaxDynamicSharedMemorySize, G1_SMEM);
    cudaFuncSetAttribute(gemm2_mma, cudaFuncAttributeMaxDynamicSharedMemorySize, G2_SMEM);

    init8_kernel<<<1, 32>>>();
    router_cvt_kernel<<<T, 256>>>(hs, gw, (const float4*)w1, (const float4*)w3,
                                  out, (const float4*)hs);
    gemm1_mma<<<dim3(F / 64, T / 128, E), 256, G1_SMEM>>>((const float4*)w2);
    gemm2_mma<<<dim3(H / 128, T / 128, E), 256, G2_SMEM>>>(out);
}